// round 7
// baseline (speedup 1.0000x reference)
#include <cuda_runtime.h>
#include <cuda_bf16.h>
#include <cstdint>

#define NPTS   8192
#define CH     32
#define TILE   256
#define MT     32                      // NPTS / TILE
#define NTILES 528                     // MT*(MT+1)/2 upper-triangle tile pairs
#define LDPW   20                      // padded row stride in b32 words (80 bytes)

// ---------------- device scratch (no allocations allowed) -------------------
__device__ float g_partial[NTILES];
__device__ int   g_counter;            // zero-init at load; reset by last CTA

// ---------------------------------------------------------------------------
// mma.sync m16n8k16 bf16 (sm_80+ baseline PTX; portable to plain sm_103).
// ---------------------------------------------------------------------------
__device__ __forceinline__ void hmma16816(float* c, const uint32_t* a, const uint32_t* b) {
    asm volatile(
        "mma.sync.aligned.m16n8k16.row.col.f32.bf16.bf16.f32 "
        "{%0,%1,%2,%3}, {%4,%5,%6,%7}, {%8,%9}, {%0,%1,%2,%3};"
        : "+f"(c[0]), "+f"(c[1]), "+f"(c[2]), "+f"(c[3])
        : "r"(a[0]), "r"(a[1]), "r"(a[2]), "r"(a[3]), "r"(b[0]), "r"(b[1]));
}

// ---------------------------------------------------------------------------
// Exact squared norm via the reference's tree pipeline (non-FMA mul/add,
// 4 accumulators). Used by cold paths; bit-identical to the hot-path version.
// ---------------------------------------------------------------------------
__device__ __forceinline__ float tree_sq(const float* __restrict__ x, int g) {
    float a0 = 0.f, a1 = 0.f, a2 = 0.f, a3 = 0.f;
#pragma unroll
    for (int c = 0; c < CH; c += 4) {
        float v0 = x[(c + 0) * NPTS + g];
        float v1 = x[(c + 1) * NPTS + g];
        float v2 = x[(c + 2) * NPTS + g];
        float v3 = x[(c + 3) * NPTS + g];
        a0 = __fadd_rn(a0, __fmul_rn(v0, v0));
        a1 = __fadd_rn(a1, __fmul_rn(v1, v1));
        a2 = __fadd_rn(a2, __fmul_rn(v2, v2));
        a3 = __fadd_rn(a3, __fmul_rn(v3, v3));
    }
    return __fadd_rn(__fadd_rn(a0, a1), __fadd_rn(a2, a3));
}

// ---------------------------------------------------------------------------
// Row loader: loads 32 channels of point g (coalesced across the warp per
// channel), computes tree-sq into *sqdst, packs bf16 into dstrow[0..15].
// If dodiag, also computes the diagonal loss term with the sequential-FMA
// self-dot (bit-identical to the passing R2..R6 prep pipeline) and returns it.
// ---------------------------------------------------------------------------
__device__ __forceinline__ float load_row(const float* __restrict__ x, int g,
                                          uint32_t* __restrict__ dstrow,
                                          float* __restrict__ sqdst, bool dodiag) {
    float a0 = 0.f, a1 = 0.f, a2 = 0.f, a3 = 0.f;
    float dot = 0.f;
#pragma unroll
    for (int ch = 0; ch < CH; ch += 8) {
        float v[8];
#pragma unroll
        for (int b = 0; b < 8; ++b) v[b] = x[(ch + b) * NPTS + g];
        // tree sq: two 4-groups, same accumulator sequence as reference pipeline
        a0 = __fadd_rn(a0, __fmul_rn(v[0], v[0]));
        a1 = __fadd_rn(a1, __fmul_rn(v[1], v[1]));
        a2 = __fadd_rn(a2, __fmul_rn(v[2], v[2]));
        a3 = __fadd_rn(a3, __fmul_rn(v[3], v[3]));
        a0 = __fadd_rn(a0, __fmul_rn(v[4], v[4]));
        a1 = __fadd_rn(a1, __fmul_rn(v[5], v[5]));
        a2 = __fadd_rn(a2, __fmul_rn(v[6], v[6]));
        a3 = __fadd_rn(a3, __fmul_rn(v[7], v[7]));
        // sequential FMA self-dot (c = 0..31 in order)
#pragma unroll
        for (int b = 0; b < 8; ++b) dot = fmaf(v[b], v[b], dot);
        // bf16 pack: 4 words per 8 channels
#pragma unroll
        for (int p = 0; p < 4; ++p) {
            __nv_bfloat162 pk = __floats2bfloat162_rn(v[2 * p], v[2 * p + 1]);
            dstrow[ch / 2 + p] = *reinterpret_cast<uint32_t*>(&pk);
        }
    }
    float sq = __fadd_rn(__fadd_rn(a0, a1), __fadd_rn(a2, a3));
    *sqdst = sq;

    float f = 0.f;
    if (dodiag) {
        float d2 = fmaf(-2.f, dot, __fadd_rn(sq, sq));
        if (d2 < 4.f) {
            d2 = fmaxf(d2, 0.f);
            float d = sqrtf(d2);
            f = fmaf(1.5f, d, fmaf(-0.5f, d2, -1.f));
        }
    }
    return f;
}

// ---------------------------------------------------------------------------
// Cold path: lane-exact fp32 recompute of this lane's 8 rows x 32 cols.
// Runs only when the bf16 screen flags (probability ~1e-9 per lane).
// ---------------------------------------------------------------------------
__device__ __noinline__ float slow_lane(const float* __restrict__ x,
                                        int I, int J, int m0, int n0,
                                        int qr, int qc) {
    float acc = 0.f;
#pragma unroll 1
    for (int r = 0; r < 8; ++r) {
        int gi = I * TILE + m0 + (r >> 1) * 16 + qr + (r & 1) * 8;
        float si = tree_sq(x, gi);
#pragma unroll 1
        for (int cidx = 0; cidx < 32; ++cidx) {
            int gj = J * TILE + n0 + (cidx >> 1) * 8 + 2 * qc + (cidx & 1);
            if (gi == gj) continue;
            float dt = 0.f;
#pragma unroll
            for (int c = 0; c < CH; ++c)
                dt = fmaf(x[c * NPTS + gi], x[c * NPTS + gj], dt);
            float e2 = fmaf(-2.f, dt, si + tree_sq(x, gj));
            if (e2 < 4.f) {
                e2 = fmaxf(e2, 0.f);
                float d = sqrtf(e2);
                acc += fmaf(1.5f, d, fmaf(-0.5f, e2, -1.f));
            }
        }
    }
    return acc;
}

// ---------------------------------------------------------------------------
// Fused kernel: one CTA per (I,J) 256x256 tile pair, J >= I, 8 warps.
// Loads + quantizes its own slabs from x, computes the bf16 HMMA screen
// (branch-free fmin tracking off-diagonal; branchy exact path on diagonal
// tiles), adds the exact diagonal loss (I==J CTAs own each point once),
// block-reduces, and lets the last CTA do the deterministic final sum.
// ---------------------------------------------------------------------------
__global__ __launch_bounds__(256) void fused_kernel(const float* __restrict__ x,
                                                    float* __restrict__ out) {
    __shared__ __align__(16) uint32_t As[TILE * LDPW];   // 20 KB
    __shared__ __align__(16) uint32_t Bs[TILE * LDPW];   // 20 KB
    __shared__ float sqA[TILE];
    __shared__ float sqB[TILE];
    __shared__ float red[256];
    __shared__ bool  amlast;

    int tid = threadIdx.x;
    int wid = tid >> 5;
    int lane = tid & 31;

    // decode blockIdx -> (I, J) over upper triangle
    int bid = blockIdx.x;
    int I = 0, rem = bid;
    while (rem >= MT - I) { rem -= MT - I; ++I; }
    int J = I + rem;
    bool diag = (I == J);

    // load + quantize slabs: thread t owns row t of each slab
    float local = load_row(x, I * TILE + tid, &As[tid * LDPW], &sqA[tid], diag);
    if (!diag)
        load_row(x, J * TILE + tid, &Bs[tid * LDPW], &sqB[tid], false);
    __syncthreads();

    const uint32_t* Bsrc = diag ? As : Bs;
    const float*    sqBv = diag ? sqA : sqB;

    int m0 = (wid & 3) * 64;     // row block of this warp (64 rows)
    int n0 = (wid >> 2) * 128;   // col block of this warp (128 cols)
    int qr = lane >> 2;          // 0..7
    int qc = lane & 3;           // 0..3

    // A fragments: afr[mi][kf][4], mi = 0..3 (16-row slabs)
    uint32_t afr[4][2][4];
#pragma unroll
    for (int mi = 0; mi < 4; ++mi) {
        int r0 = m0 + mi * 16 + qr;
        int r1 = r0 + 8;
#pragma unroll
        for (int kf = 0; kf < 2; ++kf) {
            int kw = kf * 8 + qc;
            afr[mi][kf][0] = As[r0 * LDPW + kw];
            afr[mi][kf][1] = As[r1 * LDPW + kw];
            afr[mi][kf][2] = As[r0 * LDPW + kw + 4];
            afr[mi][kf][3] = As[r1 * LDPW + kw + 4];
        }
    }

    float siv[4][2];
#pragma unroll
    for (int mi = 0; mi < 4; ++mi) {
        siv[mi][0] = sqA[m0 + mi * 16 + qr];
        siv[mi][1] = sqA[m0 + mi * 16 + qr + 8];
    }

    if (!diag) {
        // ---- hot path: branch-free screen over 16 n-fragments ----
        float dmin = 1e30f;
#pragma unroll
        for (int nj = 0; nj < 16; ++nj) {
            int jrow = n0 + nj * 8 + qr;
            uint32_t bfr[2][2];
#pragma unroll
            for (int kf = 0; kf < 2; ++kf) {
                int kw = kf * 8 + qc;
                bfr[kf][0] = Bsrc[jrow * LDPW + kw];
                bfr[kf][1] = Bsrc[jrow * LDPW + kw + 4];
            }
            float acc[4][4];
#pragma unroll
            for (int mi = 0; mi < 4; ++mi) {
                acc[mi][0] = acc[mi][1] = acc[mi][2] = acc[mi][3] = 0.f;
                hmma16816(acc[mi], afr[mi][0], bfr[0]);
                hmma16816(acc[mi], afr[mi][1], bfr[1]);
            }
            int colb = n0 + nj * 8 + 2 * qc;
            float sj0 = sqBv[colb];
            float sj1 = sqBv[colb + 1];
#pragma unroll
            for (int mi = 0; mi < 4; ++mi) {
#pragma unroll
                for (int e = 0; e < 4; ++e) {
                    float s = siv[mi][e >> 1] + ((e & 1) ? sj1 : sj0);
                    dmin = fminf(dmin, fmaf(-2.f, acc[mi][e], s));
                }
            }
        }
        float contrib = 0.f;
        if (dmin < 8.f)   // conservative screen (true cut 4, bf16 err << 4)
            contrib = slow_lane(x, I, J, m0, n0, qr, qc);
        local += 2.f * contrib;   // symmetry: (I,J) and (J,I) identical
    } else {
        // ---- diagonal tile: per-element exact path on flag ----
#pragma unroll
        for (int nj = 0; nj < 16; ++nj) {
            int jrow = n0 + nj * 8 + qr;
            uint32_t bfr[2][2];
#pragma unroll
            for (int kf = 0; kf < 2; ++kf) {
                int kw = kf * 8 + qc;
                bfr[kf][0] = Bsrc[jrow * LDPW + kw];
                bfr[kf][1] = Bsrc[jrow * LDPW + kw + 4];
            }
            float acc[4][4];
#pragma unroll
            for (int mi = 0; mi < 4; ++mi) {
                acc[mi][0] = acc[mi][1] = acc[mi][2] = acc[mi][3] = 0.f;
                hmma16816(acc[mi], afr[mi][0], bfr[0]);
                hmma16816(acc[mi], afr[mi][1], bfr[1]);
            }
            int colb = n0 + nj * 8 + 2 * qc;
            float sj0 = sqBv[colb];
            float sj1 = sqBv[colb + 1];
            int   gj0 = J * TILE + colb;
#pragma unroll
            for (int mi = 0; mi < 4; ++mi) {
#pragma unroll
                for (int e = 0; e < 4; ++e) {
                    int   rh = e >> 1;
                    float sj = (e & 1) ? sj1 : sj0;
                    int   gj = gj0 + (e & 1);
                    float si = siv[mi][rh];
                    float d2s = fmaf(-2.f, acc[mi][e], si + sj);
                    if (d2s < 8.f) {
                        int gi = I * TILE + m0 + mi * 16 + qr + rh * 8;
                        if (gi != gj) {
                            float dt = 0.f;
#pragma unroll
                            for (int c = 0; c < CH; ++c)
                                dt = fmaf(x[c * NPTS + gi], x[c * NPTS + gj], dt);
                            float e2 = fmaf(-2.f, dt, si + sj);
                            if (e2 < 4.f) {
                                e2 = fmaxf(e2, 0.f);
                                float d = sqrtf(e2);
                                local += fmaf(1.5f, d, fmaf(-0.5f, e2, -1.f));
                            }
                        }
                    }
                }
            }
        }
    }

    // deterministic block reduction
    red[tid] = local;
    __syncthreads();
#pragma unroll
    for (int s = 128; s > 0; s >>= 1) {
        if (tid < s) red[tid] += red[tid + s];
        __syncthreads();
    }
    if (tid == 0) g_partial[bid] = red[0];

    // last CTA performs the deterministic final reduction
    if (tid == 0) {
        __threadfence();
        int prev = atomicAdd(&g_counter, 1);
        amlast = (prev == NTILES - 1);
    }
    __syncthreads();
    if (amlast) {
        float s = 0.f;
        for (int i = tid; i < NTILES; i += 256) s += g_partial[i];
        red[tid] = s;
        __syncthreads();
#pragma unroll
        for (int k = 128; k > 0; k >>= 1) {
            if (tid < k) red[tid] += red[tid + k];
            __syncthreads();
        }
        if (tid == 0) {
            out[0] = 0.25f * red[0];
            g_counter = 0;           // reset for next graph replay
        }
    }
}

// ---------------------------------------------------------------------------
extern "C" void kernel_launch(void* const* d_in, const int* in_sizes, int n_in,
                              void* d_out, int out_size) {
    const float* x = (const float*)d_in[0];   // [1, 32, 8192] fp32, channel-major
    float* out = (float*)d_out;

    fused_kernel<<<NTILES, 256>>>(x, out);
}

// round 8
// speedup vs baseline: 1.1346x; 1.1346x over previous
#include <cuda_runtime.h>
#include <cuda_bf16.h>
#include <cstdint>

#define NPTS   8192
#define CH     32
#define TILE   256
#define MT     32                      // NPTS / TILE
#define NTILES 528                     // MT*(MT+1)/2 upper-triangle tile pairs
#define NPREP  128                     // prep blocks (8192 / 64)
#define PQ     12                      // padded row stride in b32 words (48B; 32B used)

// ---------------- device scratch (no allocations allowed) -------------------
__device__ float    g_sq[NPTS];           // full 32-ch tree norms (exact path)
__device__ float    g_sq16[NPTS];         // first-16-ch norms (screen only)
__device__ uint32_t g_xbf[NPTS * 8];      // [n][8] bf16x2 words: channels 0..15
__device__ float    g_partial[NTILES];
__device__ float    g_diagpart[NPREP];
__device__ int      g_counter;            // zero-init; reset by last CTA

// ---------------------------------------------------------------------------
// Kernel A (prep): per-point full tree-sq + sequential-FMA self-dot -> exact
// diagonal loss (bit-identical arithmetic to the passing R2..R6 pipeline),
// 16-ch screen norm, and bf16 pack of channels 0..15 (staged via smem for
// coalesced stores).
// ---------------------------------------------------------------------------
__global__ __launch_bounds__(64) void prep_kernel(const float* __restrict__ x) {
    __shared__ uint32_t s8[64 * 8];
    __shared__ float    red[64];

    int tid = threadIdx.x;
    int n = blockIdx.x * 64 + tid;

    float v[CH];
#pragma unroll
    for (int c = 0; c < CH; ++c) v[c] = x[c * NPTS + n];

    // full sq: non-FMA products, 4-accumulator tree (XLA-reduce flavor)
    float a0 = 0.f, a1 = 0.f, a2 = 0.f, a3 = 0.f;
#pragma unroll
    for (int c = 0; c < CH; c += 4) {
        a0 = __fadd_rn(a0, __fmul_rn(v[c + 0], v[c + 0]));
        a1 = __fadd_rn(a1, __fmul_rn(v[c + 1], v[c + 1]));
        a2 = __fadd_rn(a2, __fmul_rn(v[c + 2], v[c + 2]));
        a3 = __fadd_rn(a3, __fmul_rn(v[c + 3], v[c + 3]));
    }
    float sq = __fadd_rn(__fadd_rn(a0, a1), __fadd_rn(a2, a3));
    g_sq[n] = sq;

    // self-dot: sequential FMA chain (GEMM flavor) -> diagonal noise d2 ~ +-eps
    float dot = 0.f;
#pragma unroll
    for (int c = 0; c < CH; ++c) dot = fmaf(v[c], v[c], dot);

    float d2 = fmaf(-2.f, dot, __fadd_rn(sq, sq));
    float f = 0.f;
    if (d2 < 4.f) {
        d2 = fmaxf(d2, 0.f);
        float d = sqrtf(d2);
        f = fmaf(1.5f, d, fmaf(-0.5f, d2, -1.f));
    }

    // 16-ch screen norm (tolerance handled by screen margin)
    float s16 = 0.f;
#pragma unroll
    for (int c = 0; c < 16; ++c) s16 = fmaf(v[c], v[c], s16);
    g_sq16[n] = s16;

    // bf16 pack of channels 0..15 -> 8 words, staged for coalesced store
#pragma unroll
    for (int w = 0; w < 8; ++w) {
        __nv_bfloat162 pk = __floats2bfloat162_rn(v[2 * w], v[2 * w + 1]);
        s8[tid * 8 + w] = *reinterpret_cast<uint32_t*>(&pk);
    }
    __syncthreads();
    uint32_t* dst = &g_xbf[blockIdx.x * 64 * 8];
#pragma unroll
    for (int i = tid; i < 512; i += 64) dst[i] = s8[i];

    // deterministic block reduction of diagonal contributions
    red[tid] = f;
    __syncthreads();
#pragma unroll
    for (int s = 32; s > 0; s >>= 1) {
        if (tid < s) red[tid] += red[tid + s];
        __syncthreads();
    }
    if (tid == 0) g_diagpart[blockIdx.x] = red[0];
}

// ---------------------------------------------------------------------------
// mma.sync m16n8k16 bf16 (sm_80+ baseline PTX; portable to plain sm_103).
// ---------------------------------------------------------------------------
__device__ __forceinline__ void hmma16816(float* c, const uint32_t* a, const uint32_t* b) {
    asm volatile(
        "mma.sync.aligned.m16n8k16.row.col.f32.bf16.bf16.f32 "
        "{%0,%1,%2,%3}, {%4,%5,%6,%7}, {%8,%9}, {%0,%1,%2,%3};"
        : "+f"(c[0]), "+f"(c[1]), "+f"(c[2]), "+f"(c[3])
        : "r"(a[0]), "r"(a[1]), "r"(a[2]), "r"(a[3]), "r"(b[0]), "r"(b[1]));
}

// ---------------------------------------------------------------------------
// Exact fp32 recompute of one pair (full 32 channels). Used on screen flags.
// ---------------------------------------------------------------------------
__device__ __forceinline__ float exact_pair(const float* __restrict__ x,
                                            int gi, int gj) {
    float dt = 0.f;
#pragma unroll
    for (int c = 0; c < CH; ++c)
        dt = fmaf(x[c * NPTS + gi], x[c * NPTS + gj], dt);
    float e2 = fmaf(-2.f, dt, g_sq[gi] + g_sq[gj]);
    if (e2 < 4.f) {
        e2 = fmaxf(e2, 0.f);
        float d = sqrtf(e2);
        return fmaf(1.5f, d, fmaf(-0.5f, e2, -1.f));
    }
    return 0.f;
}

// ---------------------------------------------------------------------------
// Kernel B (tile): one CTA per (I,J) 256x256 tile pair, J >= I, 8 warps.
// K=16 bf16 HMMA screen (sound: d2_full >= d2_16). Quad-granular recovery:
// if min of a 2x2 accumulator quad < 6 (true cut 4, screen err << 2, plus
// ch16..31 >= 0), recompute flagged pairs exactly in fp32 (gi==gj skipped;
// diagonal handled in prep). mi-outer loop keeps registers low.
// Last CTA performs the deterministic final reduction.
// ---------------------------------------------------------------------------
__global__ __launch_bounds__(256, 4) void tile_kernel(const float* __restrict__ x,
                                                      float* __restrict__ out) {
    __shared__ __align__(16) uint32_t As[TILE * PQ];   // 12 KB
    __shared__ __align__(16) uint32_t Bs[TILE * PQ];   // 12 KB
    __shared__ float s16A[TILE];
    __shared__ float s16B[TILE];
    __shared__ float red[256];
    __shared__ bool  amlast;

    int tid = threadIdx.x;
    int wid = tid >> 5;
    int lane = tid & 31;

    // decode blockIdx -> (I, J) over upper triangle
    int bid = blockIdx.x;
    int I = 0, rem = bid;
    while (rem >= MT - I) { rem -= MT - I; ++I; }
    int J = I + rem;
    bool diag = (I == J);

    // fill tiles: thread t owns row t of A and row t of B (8 words = 2 uint4)
    {
        int gA = I * TILE + tid;
        const uint4* srcA = reinterpret_cast<const uint4*>(&g_xbf[gA * 8]);
        uint4* dA = reinterpret_cast<uint4*>(As + tid * PQ);
        dA[0] = srcA[0];
        dA[1] = srcA[1];
        s16A[tid] = g_sq16[gA];
        if (!diag) {
            int gB = J * TILE + tid;
            const uint4* srcB = reinterpret_cast<const uint4*>(&g_xbf[gB * 8]);
            uint4* dB = reinterpret_cast<uint4*>(Bs + tid * PQ);
            dB[0] = srcB[0];
            dB[1] = srcB[1];
            s16B[tid] = g_sq16[gB];
        }
    }
    __syncthreads();

    const uint32_t* Bsrc = diag ? As : Bs;
    const float*    sjv  = diag ? s16A : s16B;

    int m0 = (wid & 3) * 64;     // row block of this warp (64 rows)
    int n0 = (wid >> 2) * 128;   // col block of this warp (128 cols)
    int qr = lane >> 2;          // 0..7
    int qc = lane & 3;           // 0..3

    float local = 0.f;

#pragma unroll
    for (int mi = 0; mi < 4; ++mi) {
        int r0 = m0 + mi * 16 + qr;
        int r1 = r0 + 8;
        uint32_t a[4];
        a[0] = As[r0 * PQ + qc];
        a[1] = As[r1 * PQ + qc];
        a[2] = As[r0 * PQ + qc + 4];
        a[3] = As[r1 * PQ + qc + 4];
        float si0 = s16A[r0];
        float si1 = s16A[r1];

#pragma unroll
        for (int nj = 0; nj < 16; ++nj) {
            int jrow = n0 + nj * 8 + qr;
            uint32_t b[2];
            b[0] = Bsrc[jrow * PQ + qc];
            b[1] = Bsrc[jrow * PQ + qc + 4];

            float acc[4] = {0.f, 0.f, 0.f, 0.f};
            hmma16816(acc, a, b);

            int colb = n0 + nj * 8 + 2 * qc;
            float sj0 = sjv[colb];
            float sj1 = sjv[colb + 1];

            float d0 = fmaf(-2.f, acc[0], si0 + sj0);
            float d1 = fmaf(-2.f, acc[1], si0 + sj1);
            float d2 = fmaf(-2.f, acc[2], si1 + sj0);
            float d3 = fmaf(-2.f, acc[3], si1 + sj1);
            float mn = fminf(fminf(d0, d1), fminf(d2, d3));

            if (mn < 6.f) {   // rare: ~1.4e-4 per pair off-diagonal
                int gi0 = I * TILE + r0;
                int gi1 = I * TILE + r1;
                int gj0 = J * TILE + colb;
                int gj1 = gj0 + 1;
                if (d0 < 6.f && gi0 != gj0) local += exact_pair(x, gi0, gj0);
                if (d1 < 6.f && gi0 != gj1) local += exact_pair(x, gi0, gj1);
                if (d2 < 6.f && gi1 != gj0) local += exact_pair(x, gi1, gj0);
                if (d3 < 6.f && gi1 != gj1) local += exact_pair(x, gi1, gj1);
            }
        }
    }

    if (!diag) local *= 2.f;   // symmetry: (I,J) and (J,I) identical

    // deterministic block reduction
    red[tid] = local;
    __syncthreads();
#pragma unroll
    for (int s = 128; s > 0; s >>= 1) {
        if (tid < s) red[tid] += red[tid + s];
        __syncthreads();
    }
    if (tid == 0) g_partial[bid] = red[0];

    // last CTA performs the deterministic final reduction
    if (tid == 0) {
        __threadfence();
        int prev = atomicAdd(&g_counter, 1);
        amlast = (prev == NTILES - 1);
    }
    __syncthreads();
    if (amlast) {
        float s = 0.f;
        for (int i = tid; i < NTILES; i += 256) s += g_partial[i];
        for (int i = tid; i < NPREP; i += 256) s += g_diagpart[i];
        red[tid] = s;
        __syncthreads();
#pragma unroll
        for (int k = 128; k > 0; k >>= 1) {
            if (tid < k) red[tid] += red[tid + k];
            __syncthreads();
        }
        if (tid == 0) {
            out[0] = 0.25f * red[0];
            g_counter = 0;           // reset for next graph replay
        }
    }
}

// ---------------------------------------------------------------------------
extern "C" void kernel_launch(void* const* d_in, const int* in_sizes, int n_in,
                              void* d_out, int out_size) {
    const float* x = (const float*)d_in[0];   // [1, 32, 8192] fp32, channel-major
    float* out = (float*)d_out;

    prep_kernel<<<NPREP, 64>>>(x);
    tile_kernel<<<NTILES, 256>>>(x, out);
}